// round 3
// baseline (speedup 1.0000x reference)
#include <cuda_runtime.h>

#define NROWS  32768
#define DCOLS  2048
#define C4TOT  (DCOLS / 4)        // 512 float4 columns
#define SLABC4 64                 // float4 cols per slab = 256 scalar cols = 32 MB slab
#define NSLABS (C4TOT / SLABC4)   // 8
#define EPS    1e-6f

// Allocation-free scratch
__device__ float    g_u[DCOLS];
__device__ unsigned g_count;      // barrier arrival counter
__device__ unsigned g_gen;        // barrier generation (monotonic across replays)

// ---------------------------------------------------------------------------
// Grid-wide barrier. Safe iff all CTAs are co-resident (grid == numSMs,
// 1024 threads, launch_bounds(1024,1) keeps regs <= 64 so occupancy >= 1).
// Generation counter is never reset -> safe across graph replays.
__device__ __forceinline__ void grid_barrier(unsigned nblocks) {
    __syncthreads();
    if (threadIdx.x == 0) {
        __threadfence();
        unsigned my_gen = *(volatile unsigned*)&g_gen;
        unsigned arr = atomicAdd(&g_count, 1u);
        if (arr == nblocks - 1u) {
            g_count = 0u;
            __threadfence();
            atomicAdd(&g_gen, 1u);
        } else {
            while (*(volatile unsigned*)&g_gen == my_gen) { }
        }
        __threadfence();
    }
    __syncthreads();
}

// ---------------------------------------------------------------------------
// Persistent kernel: per 32MB column-slab, reduce (DRAM read, L2-allocate),
// grid barrier, then scale re-reading the slab from L2 and streaming out.
__global__ void __launch_bounds__(1024, 1)
colnorm_kernel(const float4* __restrict__ x, float4* __restrict__ y, int nblocks) {
    const int tid = threadIdx.x;
    const int c4l = tid & (SLABC4 - 1);               // 0..63: this thread's float4 col in slab
    const int rw  = (blockIdx.x << 4) + (tid >> 6);   // row-worker id: 0..16*nblocks-1
    const int W   = nblocks << 4;                     // row-workers per column

    // Zero accumulators every launch/replay
    int gid = blockIdx.x * 1024 + tid;
    if (gid < DCOLS) g_u[gid] = 0.0f;
    grid_barrier((unsigned)nblocks);

    __shared__ float sacc[SLABC4 * 4];                // 256 per-column block partials

    for (int slab = 0; slab < NSLABS; ++slab) {
        const int    C    = slab * SLABC4 + c4l;      // global float4 column
        const size_t coff = (size_t)C;

        // ---- Phase A: sum of squares over this thread's rows (MLP=4 unroll) ----
        float ax = 0.f, ay = 0.f, az = 0.f, aw = 0.f;
        int r = rw;
        for (; r + 3 * W < NROWS; r += 4 * W) {
            float4 v0 = x[(size_t)(r        ) * C4TOT + coff];
            float4 v1 = x[(size_t)(r +     W) * C4TOT + coff];
            float4 v2 = x[(size_t)(r + 2 * W) * C4TOT + coff];
            float4 v3 = x[(size_t)(r + 3 * W) * C4TOT + coff];
            ax = fmaf(v0.x, v0.x, ax); ay = fmaf(v0.y, v0.y, ay);
            az = fmaf(v0.z, v0.z, az); aw = fmaf(v0.w, v0.w, aw);
            ax = fmaf(v1.x, v1.x, ax); ay = fmaf(v1.y, v1.y, ay);
            az = fmaf(v1.z, v1.z, az); aw = fmaf(v1.w, v1.w, aw);
            ax = fmaf(v2.x, v2.x, ax); ay = fmaf(v2.y, v2.y, ay);
            az = fmaf(v2.z, v2.z, az); aw = fmaf(v2.w, v2.w, aw);
            ax = fmaf(v3.x, v3.x, ax); ay = fmaf(v3.y, v3.y, ay);
            az = fmaf(v3.z, v3.z, az); aw = fmaf(v3.w, v3.w, aw);
        }
        for (; r < NROWS; r += W) {
            float4 v = x[(size_t)r * C4TOT + coff];
            ax = fmaf(v.x, v.x, ax); ay = fmaf(v.y, v.y, ay);
            az = fmaf(v.z, v.z, az); aw = fmaf(v.w, v.w, aw);
        }

        // ---- Block-level combine, then one global atomic per column ----
        if (tid < SLABC4 * 4) sacc[tid] = 0.f;
        __syncthreads();
        atomicAdd(&sacc[c4l * 4 + 0], ax);
        atomicAdd(&sacc[c4l * 4 + 1], ay);
        atomicAdd(&sacc[c4l * 4 + 2], az);
        atomicAdd(&sacc[c4l * 4 + 3], aw);
        __syncthreads();
        if (tid < SLABC4 * 4)
            atomicAdd(&g_u[slab * SLABC4 * 4 + tid], sacc[tid]);

        grid_barrier((unsigned)nblocks);

        // ---- Per-thread scales (u is complete and L2-resident) ----
        const float4 uv = *(const float4*)&g_u[C * 4];
        const float sx = rsqrtf(uv.x + EPS);
        const float sy = rsqrtf(uv.y + EPS);
        const float sz = rsqrtf(uv.z + EPS);
        const float sw = rsqrtf(uv.w + EPS);

        // ---- Phase B: re-read slab (L2 hit), scale, stream out ----
        r = rw;
        for (; r + 3 * W < NROWS; r += 4 * W) {
            size_t o0 = (size_t)(r        ) * C4TOT + coff;
            size_t o1 = (size_t)(r +     W) * C4TOT + coff;
            size_t o2 = (size_t)(r + 2 * W) * C4TOT + coff;
            size_t o3 = (size_t)(r + 3 * W) * C4TOT + coff;
            float4 v0 = __ldcs(&x[o0]);
            float4 v1 = __ldcs(&x[o1]);
            float4 v2 = __ldcs(&x[o2]);
            float4 v3 = __ldcs(&x[o3]);
            v0.x *= sx; v0.y *= sy; v0.z *= sz; v0.w *= sw;
            v1.x *= sx; v1.y *= sy; v1.z *= sz; v1.w *= sw;
            v2.x *= sx; v2.y *= sy; v2.z *= sz; v2.w *= sw;
            v3.x *= sx; v3.y *= sy; v3.z *= sz; v3.w *= sw;
            __stcs(&y[o0], v0);
            __stcs(&y[o1], v1);
            __stcs(&y[o2], v2);
            __stcs(&y[o3], v3);
        }
        for (; r < NROWS; r += W) {
            size_t o = (size_t)r * C4TOT + coff;
            float4 v = __ldcs(&x[o]);
            v.x *= sx; v.y *= sy; v.z *= sz; v.w *= sw;
            __stcs(&y[o], v);
        }
        // No barrier here: next slab's reduce touches disjoint g_u entries,
        // and its DRAM reads usefully overlap stragglers' phase B.
    }
}

// ---------------------------------------------------------------------------
extern "C" void kernel_launch(void* const* d_in, const int* in_sizes, int n_in,
                              void* d_out, int out_size) {
    const float4* x = (const float4*)d_in[0];
    float4*       y = (float4*)d_out;

    static int nsm = 0;
    if (nsm == 0) {
        cudaDeviceProp prop;
        cudaGetDeviceProperties(&prop, 0);
        nsm = prop.multiProcessorCount;   // 152 on GB300
    }

    colnorm_kernel<<<nsm, 1024>>>(x, y, nsm);
}

// round 5
// speedup vs baseline: 1.1584x; 1.1584x over previous
#include <cuda_runtime.h>

#define NROWS   32768
#define DCOLS   2048
#define C4TOT   (DCOLS / 4)          // 512 float4 columns per row
#define SLABC4  128                  // float4 cols per slab = 512 scalar cols = 64 MB
#define NSLABS  (C4TOT / SLABC4)     // 4
#define EPS     1e-6f

// Allocation-free scratch (__device__ globals). Returned to zero by the
// kernels themselves, so graph replays see identical initial state.
__device__ float g_u[DCOLS];         // column sum-of-squares accumulators
__device__ float g_s[DCOLS];         // rsqrt scales
__device__ int   g_cnt[DCOLS];       // per-column arrival counters

// ---------------------------------------------------------------------------
// Phase A: reduce one 64MB slab. Grid = G blocks x 512 threads.
// Block layout: tid&127 -> float4 col within slab, tid>>7 -> row sub-worker.
// Publication protocol per contributor: atomicAdd(g_u) -> threadfence ->
// atomicAdd(g_cnt). The thread that observes arrival G-1 knows ALL g_u adds
// are globally visible, so it atomically swaps the total out (and zeroes the
// accumulator for the next replay) with atomicExch.
__global__ void __launch_bounds__(512)
reduceA_kernel(const float4* __restrict__ x, int slab, int G) {
    const int tid = threadIdx.x;
    const int c4l = tid & (SLABC4 - 1);             // 0..127
    const int w   = (blockIdx.x << 2) + (tid >> 7); // row worker id
    const int W   = G << 2;                         // total row workers
    const size_t coff = (size_t)slab * SLABC4 + c4l;

    float ax = 0.f, ay = 0.f, az = 0.f, aw = 0.f;
    int r = w;
    for (; r + 3 * W < NROWS; r += 4 * W) {
        float4 v0 = x[(size_t)(r        ) * C4TOT + coff];
        float4 v1 = x[(size_t)(r +     W) * C4TOT + coff];
        float4 v2 = x[(size_t)(r + 2 * W) * C4TOT + coff];
        float4 v3 = x[(size_t)(r + 3 * W) * C4TOT + coff];
        ax = fmaf(v0.x, v0.x, ax); ay = fmaf(v0.y, v0.y, ay);
        az = fmaf(v0.z, v0.z, az); aw = fmaf(v0.w, v0.w, aw);
        ax = fmaf(v1.x, v1.x, ax); ay = fmaf(v1.y, v1.y, ay);
        az = fmaf(v1.z, v1.z, az); aw = fmaf(v1.w, v1.w, aw);
        ax = fmaf(v2.x, v2.x, ax); ay = fmaf(v2.y, v2.y, ay);
        az = fmaf(v2.z, v2.z, az); aw = fmaf(v2.w, v2.w, aw);
        ax = fmaf(v3.x, v3.x, ax); ay = fmaf(v3.y, v3.y, ay);
        az = fmaf(v3.z, v3.z, az); aw = fmaf(v3.w, v3.w, aw);
    }
    for (; r < NROWS; r += W) {
        float4 v = x[(size_t)r * C4TOT + coff];
        ax = fmaf(v.x, v.x, ax); ay = fmaf(v.y, v.y, ay);
        az = fmaf(v.z, v.z, az); aw = fmaf(v.w, v.w, aw);
    }

    // Combine the 4 row-workers per column in shared memory (no atomics:
    // each (worker, scalar-col) slot is unique).
    __shared__ float sacc[4][SLABC4 * 4];
    const int rw = tid >> 7;
    sacc[rw][c4l * 4 + 0] = ax;
    sacc[rw][c4l * 4 + 1] = ay;
    sacc[rw][c4l * 4 + 2] = az;
    sacc[rw][c4l * 4 + 3] = aw;
    __syncthreads();

    // 512 threads -> 512 scalar columns of this slab
    const int scol = slab * (SLABC4 * 4) + tid;     // global scalar column
    float v = sacc[0][tid] + sacc[1][tid] + sacc[2][tid] + sacc[3][tid];
    atomicAdd(&g_u[scol], v);
    __threadfence();                                 // publish before counting
    int arrived = atomicAdd(&g_cnt[scol], 1);
    if (arrived == G - 1) {                          // everyone has published
        float total = atomicExch(&g_u[scol], 0.0f);  // read complete sum + reset
        g_s[scol]   = rsqrtf(total + EPS);
        g_cnt[scol] = 0;                             // reset for next replay
    }
}

// ---------------------------------------------------------------------------
// Phase B: stream one slab: y = x * s[col]. Reads hit L2 (slab was just
// allocated by phase A); ldcs/stcs mark lines evict-first so the consumed
// slab lines and the write-back traffic free L2 for the next slab.
__global__ void __launch_bounds__(256)
scaleB_kernel(const float4* __restrict__ x, float4* __restrict__ y, int slab) {
    const int i   = blockIdx.x * 256 + threadIdx.x;  // slab-local float4 index
    const int row = i >> 7;                          // /SLABC4
    const int c4l = i & (SLABC4 - 1);
    const size_t o = (size_t)row * C4TOT + (size_t)slab * SLABC4 + c4l;

    const float4 s = ((const float4*)g_s)[slab * SLABC4 + c4l];
    float4 v = __ldcs(&x[o]);
    v.x *= s.x; v.y *= s.y; v.z *= s.z; v.w *= s.w;
    __stcs(&y[o], v);
}

// ---------------------------------------------------------------------------
extern "C" void kernel_launch(void* const* d_in, const int* in_sizes, int n_in,
                              void* d_out, int out_size) {
    const float4* x = (const float4*)d_in[0];
    float4*       y = (float4*)d_out;

    static int nsm = 0;
    if (nsm == 0) {
        cudaDeviceProp prop;
        cudaGetDeviceProperties(&prop, 0);
        nsm = prop.multiProcessorCount;               // 152 on GB300
    }
    const int G = 2 * nsm;                            // even waves for phase A

    const unsigned bBlocks = (NROWS * SLABC4) / 256;  // 16384 per slab

    for (int slab = 0; slab < NSLABS; ++slab) {
        reduceA_kernel<<<G, 512>>>(x, slab, G);
        scaleB_kernel<<<bBlocks, 256>>>(x, y, slab);
    }
}